// round 5
// baseline (speedup 1.0000x reference)
#include <cuda_runtime.h>
#include <cstdint>

// Problem constants
#define NNv 5
#define F_INv 128
#define NACTv 8
#define ROWS 32768
#define CHUNKS (ROWS / 4)         // 8192 chunks of 4 rows
#define ROW_F 5120                // floats per (b,j) row of y

#define NTHREADS 384
#define NWARPS 12
#define GRID 152

// dynamic smem layout, offsets in floats
#define OFF_WE0 0          // 128*128 = 16384
#define OFF_WE1 16384      // 128*32  = 4096
#define OFF_W1  20480      // 32*32
#define OFF_W2  21504
#define OFF_W3  22528
#define OFF_W4P 23552      // [8][32] fused W4@Wp
#define OFF_BE0 23808      // 128
#define OFF_BE1 23936      // 32
#define OFF_B1  23968
#define OFF_B2  24000
#define OFF_B3  24032
#define OFF_B4P 24064      // 8 (pad to 32)
#define OFF_XBUF 24096     // 12 warps * 512 floats
#define OFF_YBUF 30240     // 12 warps * 2048 floats (4 slots x 512)
#define SMEM_FLOATS (30240 + 12 * 2048)   // 54816
#define SMEM_BYTES (SMEM_FLOATS * 4)      // 219264 B

__device__ unsigned int g_ctr;

__device__ __forceinline__ float warpsum(float v) {
    v += __shfl_xor_sync(0xffffffffu, v, 16);
    v += __shfl_xor_sync(0xffffffffu, v, 8);
    v += __shfl_xor_sync(0xffffffffu, v, 4);
    v += __shfl_xor_sync(0xffffffffu, v, 2);
    v += __shfl_xor_sync(0xffffffffu, v, 1);
    return v;
}

__device__ __forceinline__ void fma4(float4& a, float s, const float4& w) {
    a.x = fmaf(s, w.x, a.x);
    a.y = fmaf(s, w.y, a.y);
    a.z = fmaf(s, w.z, a.z);
    a.w = fmaf(s, w.w, a.w);
}

__device__ __forceinline__ uint32_t smem_u32(const void* p) {
    uint32_t a;
    asm("{ .reg .u64 t; cvta.to.shared.u64 t, %1; cvt.u32.u64 %0, t; }"
        : "=r"(a) : "l"(p));
    return a;
}
__device__ __forceinline__ void cp16(uint32_t s, const void* g) {
    asm volatile("cp.async.cg.shared.global [%0], [%1], 16;" :: "r"(s), "l"(g));
}
__device__ __forceinline__ void cp_commit() {
    asm volatile("cp.async.commit_group;" ::: "memory");
}
template <int N> __device__ __forceinline__ void cp_wait() {
    asm volatile("cp.async.wait_group %0;" :: "n"(N) : "memory");
}

// issue one 2KB slice: lane copies 4x16B (stride 512B)
__device__ __forceinline__ void issue_slice(uint32_t sdst, const float* gsrc) {
    cp16(sdst,        gsrc);
    cp16(sdst + 512,  gsrc + 128);
    cp16(sdst + 1024, gsrc + 256);
    cp16(sdst + 1536, gsrc + 384);
    cp_commit();
}

__global__ __launch_bounds__(NTHREADS, 1) void fused_kernel(
    const float* __restrict__ x,
    const float* __restrict__ y,
    const float* __restrict__ We0, const float* __restrict__ be0,
    const float* __restrict__ We1, const float* __restrict__ be1,
    const float* __restrict__ W1, const float* __restrict__ b1,
    const float* __restrict__ W2, const float* __restrict__ b2,
    const float* __restrict__ W3, const float* __restrict__ b3,
    const float* __restrict__ W4, const float* __restrict__ b4,
    const float* __restrict__ Wp, const float* __restrict__ bp,
    float* __restrict__ out)
{
    extern __shared__ float sm[];
    const int tid  = threadIdx.x;
    const int lane = tid & 31;
    const int w    = tid >> 5;

    // ---- cooperative weight load into smem ----
    for (int i = tid; i < 16384; i += NTHREADS) sm[OFF_WE0 + i] = We0[i];
    for (int i = tid; i < 4096;  i += NTHREADS) sm[OFF_WE1 + i] = We1[i];
    for (int i = tid; i < 1024;  i += NTHREADS) {
        sm[OFF_W1 + i] = W1[i];
        sm[OFF_W2 + i] = W2[i];
        sm[OFF_W3 + i] = W3[i];
    }
    // fused head: W4p[a][e] = sum_k W4[e][k]*Wp[k][a]; b4p = b4@Wp + bp
    if (tid < 256) {
        const int a = tid >> 5, e = tid & 31;
        float acc = 0.f;
        #pragma unroll 8
        for (int k = 0; k < 32; k++)
            acc = fmaf(W4[e * 32 + k], Wp[k * NACTv + a], acc);
        sm[OFF_W4P + a * 32 + e] = acc;
    }
    if (tid < 128) sm[OFF_BE0 + tid] = be0[tid];
    if (tid < 32) {
        sm[OFF_BE1 + tid] = be1[tid];
        sm[OFF_B1 + tid] = b1[tid];
        sm[OFF_B2 + tid] = b2[tid];
        sm[OFF_B3 + tid] = b3[tid];
        if (tid < 8) {
            float acc = bp[tid];
            #pragma unroll 8
            for (int k = 0; k < 32; k++)
                acc = fmaf(b4[k], Wp[k * NACTv + tid], acc);
            sm[OFF_B4P + tid] = acc;
        }
    }
    __syncthreads();

    const float4* We0s4 = (const float4*)(sm + OFF_WE0);
    const float4* be0s4 = (const float4*)(sm + OFF_BE0);
    float4* xb4 = (float4*)(sm + OFF_XBUF) + w * 128;      // 4 rows x 32 float4
    float* ybuf = sm + OFF_YBUF + w * 2048;                 // 4 slots x 512 floats
    const uint32_t ybase = smem_u32(ybuf) + (uint32_t)lane * 16;

    const float b1v  = sm[OFF_B1 + lane];
    const float b2v  = sm[OFF_B2 + lane];
    const float b3v  = sm[OFF_B3 + lane];
    const float be1v = sm[OFF_BE1 + lane];

    // ---- warp-level work stealing over 4-row chunks ----
    for (;;) {
        unsigned int c;
        if (lane == 0) c = atomicAdd(&g_ctr, 1u);
        c = __shfl_sync(0xffffffffu, c, 0);
        if (c >= CHUNKS) break;
        const int row0 = (int)c * 4;
        const float* ychunk = y + (size_t)row0 * ROW_F + lane * 4;

        // ---- prologue: issue y slices 0..3 (stay in flight through MLP) ----
        #pragma unroll
        for (int s = 0; s < 4; s++)
            issue_slice(ybase + (s & 3) * 2048, ychunk + s * 512);

        // ---- stage x (4 rows) into per-warp smem ----
        #pragma unroll
        for (int r = 0; r < 4; r++)
            xb4[r * 32 + lane] = ((const float4*)(x + (size_t)(row0 + r) * F_INv))[lane];
        __syncwarp();

        // ---- layer 0: lane owns features lane*4..lane*4+3 ----
        float4 acc0 = be0s4[lane], acc1 = acc0, acc2 = acc0, acc3 = acc0;
        #pragma unroll 8
        for (int k4 = 0; k4 < 32; k4++) {
            float4 w0 = We0s4[(k4 * 4 + 0) * 32 + lane];
            float4 w1 = We0s4[(k4 * 4 + 1) * 32 + lane];
            float4 w2 = We0s4[(k4 * 4 + 2) * 32 + lane];
            float4 w3 = We0s4[(k4 * 4 + 3) * 32 + lane];
            float4 xk;
            xk = xb4[0 * 32 + k4];
            fma4(acc0, xk.x, w0); fma4(acc0, xk.y, w1); fma4(acc0, xk.z, w2); fma4(acc0, xk.w, w3);
            xk = xb4[1 * 32 + k4];
            fma4(acc1, xk.x, w0); fma4(acc1, xk.y, w1); fma4(acc1, xk.z, w2); fma4(acc1, xk.w, w3);
            xk = xb4[2 * 32 + k4];
            fma4(acc2, xk.x, w0); fma4(acc2, xk.y, w1); fma4(acc2, xk.z, w2); fma4(acc2, xk.w, w3);
            xk = xb4[3 * 32 + k4];
            fma4(acc3, xk.x, w0); fma4(acc3, xk.y, w1); fma4(acc3, xk.z, w2); fma4(acc3, xk.w, w3);
        }
        __syncwarp();
        acc0.x = fmaxf(acc0.x, 0.f); acc0.y = fmaxf(acc0.y, 0.f); acc0.z = fmaxf(acc0.z, 0.f); acc0.w = fmaxf(acc0.w, 0.f);
        acc1.x = fmaxf(acc1.x, 0.f); acc1.y = fmaxf(acc1.y, 0.f); acc1.z = fmaxf(acc1.z, 0.f); acc1.w = fmaxf(acc1.w, 0.f);
        acc2.x = fmaxf(acc2.x, 0.f); acc2.y = fmaxf(acc2.y, 0.f); acc2.z = fmaxf(acc2.z, 0.f); acc2.w = fmaxf(acc2.w, 0.f);
        acc3.x = fmaxf(acc3.x, 0.f); acc3.y = fmaxf(acc3.y, 0.f); acc3.z = fmaxf(acc3.z, 0.f); acc3.w = fmaxf(acc3.w, 0.f);
        xb4[0 * 32 + lane] = acc0;
        xb4[1 * 32 + lane] = acc1;
        xb4[2 * 32 + lane] = acc2;
        xb4[3 * 32 + lane] = acc3;
        __syncwarp();

        // ---- layer 1: lane owns output dim `lane` ----
        float a1_0 = be1v, a1_1 = be1v, a1_2 = be1v, a1_3 = be1v;
        #pragma unroll 8
        for (int k4 = 0; k4 < 32; k4++) {
            float w0 = sm[OFF_WE1 + (k4 * 4 + 0) * 32 + lane];
            float w1 = sm[OFF_WE1 + (k4 * 4 + 1) * 32 + lane];
            float w2 = sm[OFF_WE1 + (k4 * 4 + 2) * 32 + lane];
            float w3 = sm[OFF_WE1 + (k4 * 4 + 3) * 32 + lane];
            float4 hk;
            hk = xb4[0 * 32 + k4];
            a1_0 = fmaf(hk.x, w0, a1_0); a1_0 = fmaf(hk.y, w1, a1_0); a1_0 = fmaf(hk.z, w2, a1_0); a1_0 = fmaf(hk.w, w3, a1_0);
            hk = xb4[1 * 32 + k4];
            a1_1 = fmaf(hk.x, w0, a1_1); a1_1 = fmaf(hk.y, w1, a1_1); a1_1 = fmaf(hk.z, w2, a1_1); a1_1 = fmaf(hk.w, w3, a1_1);
            hk = xb4[2 * 32 + k4];
            a1_2 = fmaf(hk.x, w0, a1_2); a1_2 = fmaf(hk.y, w1, a1_2); a1_2 = fmaf(hk.z, w2, a1_2); a1_2 = fmaf(hk.w, w3, a1_2);
            hk = xb4[3 * 32 + k4];
            a1_3 = fmaf(hk.x, w0, a1_3); a1_3 = fmaf(hk.y, w1, a1_3); a1_3 = fmaf(hk.z, w2, a1_3); a1_3 = fmaf(hk.w, w3, a1_3);
        }
        float h[4];
        h[0] = fmaxf(a1_0, 0.f); h[1] = fmaxf(a1_1, 0.f);
        h[2] = fmaxf(a1_2, 0.f); h[3] = fmaxf(a1_3, 0.f);

        // ---- g1/g2/g3 = h@W1..W3 for all 4 rows ----
        float g1[4], g2[4], g3[4];
        #pragma unroll
        for (int r = 0; r < 4; r++) { g1[r] = b1v; g2[r] = 0.f; g3[r] = 0.f; }
        #pragma unroll 8
        for (int e = 0; e < 32; e++) {
            const float w1e = sm[OFF_W1 + e * 32 + lane];
            const float w2e = sm[OFF_W2 + e * 32 + lane];
            const float w3e = sm[OFF_W3 + e * 32 + lane];
            #pragma unroll
            for (int r = 0; r < 4; r++) {
                const float he = __shfl_sync(0xffffffffu, h[r], e);
                g1[r] = fmaf(he, w1e, g1[r]);
                g2[r] = fmaf(he, w2e, g2[r]);
                g3[r] = fmaf(he, w3e, g3[r]);
            }
        }
        #pragma unroll
        for (int r = 0; r < 4; r++) g1[r] = fmaxf(g1[r], 0.f);

        // ---- drain: 40 slices (r-major, n, half); wait / reduce / reissue ----
        float ys[4][NNv];
        float part = 0.f;
        #pragma unroll
        for (int s = 0; s < 40; s++) {
            if (s < 37)      cp_wait<3>();
            else if (s == 37) cp_wait<2>();
            else if (s == 38) cp_wait<1>();
            else              cp_wait<0>();

            const float4* sb = (const float4*)(ybuf + (s & 3) * 512);
            float acc = 0.f;
            #pragma unroll
            for (int j = 0; j < 4; j++) {
                float4 v = sb[lane + j * 32];
                acc += (v.x + v.y) + (v.z + v.w);
            }
            if ((s & 1) == 0) part = acc;
            else ys[s / 10][(s % 10) >> 1] = warpsum(part + acc);

            if (s + 4 < 40)
                issue_slice(ybase + ((s + 4) & 3) * 2048, ychunk + (s + 4) * 512);
        }

        // ---- per-row epilogue ----
        #pragma unroll
        for (int r = 0; r < 4; r++) {
            const int row = row0 + r;

            float sc[NNv];
            #pragma unroll
            for (int n = 0; n < NNv; n++)
                sc[n] = warpsum(g1[r] * fmaxf(fmaf(ys[r][n], g2[r], b2v), 0.0f));

            float m = sc[0];
            #pragma unroll
            for (int n = 1; n < NNv; n++) m = fmaxf(m, sc[n]);
            float att[NNv], denom = 0.0f;
            #pragma unroll
            for (int n = 0; n < NNv; n++) { att[n] = __expf(sc[n] - m); denom += att[n]; }
            const float inv = 1.0f / denom;
            float sv = 0.0f;
            #pragma unroll
            for (int n = 0; n < NNv; n++) { att[n] *= inv; sv = fmaf(att[n], ys[r][n], sv); }

            // ctx_d = s*g3_d + b3_d; logits = ctx @ W4p^T + b4p (fused head)
            const float ctxd = fmaf(sv, g3[r], b3v);
            float la = 0.0f;
            #pragma unroll
            for (int a = 0; a < NACTv; a++) {
                float p = warpsum(ctxd * sm[OFF_W4P + a * 32 + lane]);
                if (lane == a) la = p;
            }
            if (lane < NACTv)
                out[(size_t)row * NACTv + lane] = la + sm[OFF_B4P + lane];

            float av = 0.0f;
            #pragma unroll
            for (int n = 0; n < NNv; n++) if (lane == n) av = att[n];
            if (lane < NNv)
                out[(size_t)ROWS * NACTv + (size_t)row * NNv + lane] = av;
        }
    }
}

// ---------------------------------------------------------------------------
extern "C" void kernel_launch(void* const* d_in, const int* in_sizes, int n_in,
                              void* d_out, int out_size)
{
    const float* x   = (const float*)d_in[0];
    const float* y   = (const float*)d_in[1];
    const float* We0 = (const float*)d_in[2];
    const float* be0 = (const float*)d_in[3];
    const float* We1 = (const float*)d_in[4];
    const float* be1 = (const float*)d_in[5];
    const float* W1  = (const float*)d_in[6];
    const float* b1  = (const float*)d_in[7];
    const float* W2  = (const float*)d_in[8];
    const float* b2  = (const float*)d_in[9];
    const float* W3  = (const float*)d_in[10];
    const float* b3  = (const float*)d_in[11];
    const float* W4  = (const float*)d_in[12];
    const float* b4  = (const float*)d_in[13];
    const float* Wp  = (const float*)d_in[14];
    const float* bp  = (const float*)d_in[15];
    float* out = (float*)d_out;

    cudaFuncSetAttribute(fused_kernel, cudaFuncAttributeMaxDynamicSharedMemorySize, SMEM_BYTES);

    void* ctr_ptr = nullptr;
    cudaGetSymbolAddress(&ctr_ptr, g_ctr);
    cudaMemsetAsync(ctr_ptr, 0, sizeof(unsigned int));

    fused_kernel<<<GRID, NTHREADS, SMEM_BYTES>>>(
        x, y, We0, be0, We1, be1, W1, b1, W2, b2, W3, b3, W4, b4, Wp, bp, out);
}

// round 7
// speedup vs baseline: 1.1931x; 1.1931x over previous
#include <cuda_runtime.h>
#include <cstdint>

// Problem constants
#define NNv 5
#define NACTv 8
#define ROWS 32768
#define CHUNKS 8192               // chunks of 4 rows
#define ROW_F 5120                // floats per (b,j) row of y

#define NTHREADS 576              // 18 warps: 12 streamers + 6 MLP producers
#define NSTREAM 12
#define NMLP 6
#define GRID 152

// dynamic smem layout, offsets in floats
#define OFF_WE0 0          // 128*128 = 16384
#define OFF_WE1 16384      // 128*32  = 4096
#define OFF_W1  20480      // 32*32
#define OFF_W2  21504
#define OFF_W3  22528
#define OFF_W4P 23552      // [8][32] fused W4@Wp
#define OFF_BE0 23808      // 128
#define OFF_BE1 23936      // 32
#define OFF_B1  23968
#define OFF_B2  24000
#define OFF_B3  24032
#define OFF_B4P 24064      // 8 (pad 32)
#define OFF_GBUF 24096     // 12 streamers * 2 slots * 384 floats = 9216
#define OFF_XBUF 33312     // 6 mlp warps * 512 floats = 3072
#define OFF_PROD 36384     // 24 ints (12 streamers x 2 slots)
#define OFF_CONS 36408     // 12 ints
#define SMEM_FLOATS 36424
#define SMEM_BYTES (SMEM_FLOATS * 4)   // ~145.7 KB

__device__ __forceinline__ float warpsum(float v) {
    v += __shfl_xor_sync(0xffffffffu, v, 16);
    v += __shfl_xor_sync(0xffffffffu, v, 8);
    v += __shfl_xor_sync(0xffffffffu, v, 4);
    v += __shfl_xor_sync(0xffffffffu, v, 2);
    v += __shfl_xor_sync(0xffffffffu, v, 1);
    return v;
}

__device__ __forceinline__ void fma4(float4& a, float s, const float4& w) {
    a.x = fmaf(s, w.x, a.x);
    a.y = fmaf(s, w.y, a.y);
    a.z = fmaf(s, w.z, a.z);
    a.w = fmaf(s, w.w, a.w);
}

__global__ __launch_bounds__(NTHREADS, 1) void fused_kernel(
    const float* __restrict__ x,
    const float* __restrict__ y,
    const float* __restrict__ We0, const float* __restrict__ be0,
    const float* __restrict__ We1, const float* __restrict__ be1,
    const float* __restrict__ W1, const float* __restrict__ b1,
    const float* __restrict__ W2, const float* __restrict__ b2,
    const float* __restrict__ W3, const float* __restrict__ b3,
    const float* __restrict__ W4, const float* __restrict__ b4,
    const float* __restrict__ Wp, const float* __restrict__ bp,
    float* __restrict__ out)
{
    extern __shared__ float sm[];
    const int tid  = threadIdx.x;
    const int lane = tid & 31;
    const int w    = tid >> 5;
    const int b    = blockIdx.x;

    // ---- cooperative weight load into smem ----
    for (int i = tid; i < 16384; i += NTHREADS) sm[OFF_WE0 + i] = We0[i];
    for (int i = tid; i < 4096;  i += NTHREADS) sm[OFF_WE1 + i] = We1[i];
    for (int i = tid; i < 1024;  i += NTHREADS) {
        sm[OFF_W1 + i] = W1[i];
        sm[OFF_W2 + i] = W2[i];
        sm[OFF_W3 + i] = W3[i];
    }
    // fused head: W4p[a][e] = sum_k W4[e][k]*Wp[k][a]; b4p = b4@Wp + bp
    if (tid < 256) {
        const int a = tid >> 5, e = tid & 31;
        float acc = 0.f;
        #pragma unroll 8
        for (int k = 0; k < 32; k++)
            acc = fmaf(W4[e * 32 + k], Wp[k * NACTv + a], acc);
        sm[OFF_W4P + a * 32 + e] = acc;
    }
    if (tid < 128) sm[OFF_BE0 + tid] = be0[tid];
    if (tid < 32) {
        sm[OFF_BE1 + tid] = be1[tid];
        sm[OFF_B1 + tid] = b1[tid];
        sm[OFF_B2 + tid] = b2[tid];
        sm[OFF_B3 + tid] = b3[tid];
        if (tid < 8) {
            float acc = bp[tid];
            #pragma unroll 8
            for (int k = 0; k < 32; k++)
                acc = fmaf(b4[k], Wp[k * NACTv + tid], acc);
            sm[OFF_B4P + tid] = acc;
        }
    }
    // flags
    int* prod = (int*)(sm + OFF_PROD);
    int* cons = (int*)(sm + OFF_CONS);
    if (tid < 24) prod[tid] = -1;
    if (tid < 12) cons[tid] = tid - 12;   // allows producer 2-slot lookahead
    __syncthreads();

    volatile int* vprod = (volatile int*)prod;
    volatile int* vcons = (volatile int*)cons;

    if (w >= NSTREAM) {
        // ===================== PRODUCER (MLP) warps =====================
        const int mw = w - NSTREAM;
        const float4* We0s4 = (const float4*)(sm + OFF_WE0);
        const float4* be0s4 = (const float4*)(sm + OFF_BE0);
        float4* xb4 = (float4*)(sm + OFF_XBUF) + mw * 128;
        const float b1v  = sm[OFF_B1 + lane];
        const float be1v = sm[OFF_BE1 + lane];

        for (int k = mw; ; k += NMLP) {
            const int gchunk = b + GRID * k;
            if (gchunk >= CHUNKS) break;
            const int row0 = gchunk * 4;
            const int s = k % NSTREAM;
            const int slot = (k / NSTREAM) & 1;

            // wait for slot free (consumer done with k-24)
            while (vcons[s] < k - 2 * NSTREAM) { }

            // stage x
            #pragma unroll
            for (int r = 0; r < 4; r++)
                xb4[r * 32 + lane] = __ldcs(((const float4*)(x)) + (size_t)(row0 + r) * 32 + lane);
            __syncwarp();

            // layer 0
            float4 acc0 = be0s4[lane], acc1 = acc0, acc2 = acc0, acc3 = acc0;
            #pragma unroll 8
            for (int k4 = 0; k4 < 32; k4++) {
                float4 w0 = We0s4[(k4 * 4 + 0) * 32 + lane];
                float4 w1 = We0s4[(k4 * 4 + 1) * 32 + lane];
                float4 w2 = We0s4[(k4 * 4 + 2) * 32 + lane];
                float4 w3 = We0s4[(k4 * 4 + 3) * 32 + lane];
                float4 xk;
                xk = xb4[0 * 32 + k4];
                fma4(acc0, xk.x, w0); fma4(acc0, xk.y, w1); fma4(acc0, xk.z, w2); fma4(acc0, xk.w, w3);
                xk = xb4[1 * 32 + k4];
                fma4(acc1, xk.x, w0); fma4(acc1, xk.y, w1); fma4(acc1, xk.z, w2); fma4(acc1, xk.w, w3);
                xk = xb4[2 * 32 + k4];
                fma4(acc2, xk.x, w0); fma4(acc2, xk.y, w1); fma4(acc2, xk.z, w2); fma4(acc2, xk.w, w3);
                xk = xb4[3 * 32 + k4];
                fma4(acc3, xk.x, w0); fma4(acc3, xk.y, w1); fma4(acc3, xk.z, w2); fma4(acc3, xk.w, w3);
            }
            __syncwarp();
            acc0.x = fmaxf(acc0.x, 0.f); acc0.y = fmaxf(acc0.y, 0.f); acc0.z = fmaxf(acc0.z, 0.f); acc0.w = fmaxf(acc0.w, 0.f);
            acc1.x = fmaxf(acc1.x, 0.f); acc1.y = fmaxf(acc1.y, 0.f); acc1.z = fmaxf(acc1.z, 0.f); acc1.w = fmaxf(acc1.w, 0.f);
            acc2.x = fmaxf(acc2.x, 0.f); acc2.y = fmaxf(acc2.y, 0.f); acc2.z = fmaxf(acc2.z, 0.f); acc2.w = fmaxf(acc2.w, 0.f);
            acc3.x = fmaxf(acc3.x, 0.f); acc3.y = fmaxf(acc3.y, 0.f); acc3.z = fmaxf(acc3.z, 0.f); acc3.w = fmaxf(acc3.w, 0.f);
            xb4[0 * 32 + lane] = acc0;
            xb4[1 * 32 + lane] = acc1;
            xb4[2 * 32 + lane] = acc2;
            xb4[3 * 32 + lane] = acc3;
            __syncwarp();

            // layer 1
            float a1_0 = be1v, a1_1 = be1v, a1_2 = be1v, a1_3 = be1v;
            #pragma unroll 8
            for (int k4 = 0; k4 < 32; k4++) {
                float w0 = sm[OFF_WE1 + (k4 * 4 + 0) * 32 + lane];
                float w1 = sm[OFF_WE1 + (k4 * 4 + 1) * 32 + lane];
                float w2 = sm[OFF_WE1 + (k4 * 4 + 2) * 32 + lane];
                float w3 = sm[OFF_WE1 + (k4 * 4 + 3) * 32 + lane];
                float4 hk;
                hk = xb4[0 * 32 + k4];
                a1_0 = fmaf(hk.x, w0, a1_0); a1_0 = fmaf(hk.y, w1, a1_0); a1_0 = fmaf(hk.z, w2, a1_0); a1_0 = fmaf(hk.w, w3, a1_0);
                hk = xb4[1 * 32 + k4];
                a1_1 = fmaf(hk.x, w0, a1_1); a1_1 = fmaf(hk.y, w1, a1_1); a1_1 = fmaf(hk.z, w2, a1_1); a1_1 = fmaf(hk.w, w3, a1_1);
                hk = xb4[2 * 32 + k4];
                a1_2 = fmaf(hk.x, w0, a1_2); a1_2 = fmaf(hk.y, w1, a1_2); a1_2 = fmaf(hk.z, w2, a1_2); a1_2 = fmaf(hk.w, w3, a1_2);
                hk = xb4[3 * 32 + k4];
                a1_3 = fmaf(hk.x, w0, a1_3); a1_3 = fmaf(hk.y, w1, a1_3); a1_3 = fmaf(hk.z, w2, a1_3); a1_3 = fmaf(hk.w, w3, a1_3);
            }
            float h[4];
            h[0] = fmaxf(a1_0, 0.f); h[1] = fmaxf(a1_1, 0.f);
            h[2] = fmaxf(a1_2, 0.f); h[3] = fmaxf(a1_3, 0.f);

            // g1/g2/g3
            float g1[4], g2[4], g3[4];
            #pragma unroll
            for (int r = 0; r < 4; r++) { g1[r] = b1v; g2[r] = 0.f; g3[r] = 0.f; }
            #pragma unroll 8
            for (int e = 0; e < 32; e++) {
                const float w1e = sm[OFF_W1 + e * 32 + lane];
                const float w2e = sm[OFF_W2 + e * 32 + lane];
                const float w3e = sm[OFF_W3 + e * 32 + lane];
                #pragma unroll
                for (int r = 0; r < 4; r++) {
                    const float he = __shfl_sync(0xffffffffu, h[r], e);
                    g1[r] = fmaf(he, w1e, g1[r]);
                    g2[r] = fmaf(he, w2e, g2[r]);
                    g3[r] = fmaf(he, w3e, g3[r]);
                }
            }

            // publish to slot
            float* gs = sm + OFF_GBUF + (s * 2 + slot) * 384;
            #pragma unroll
            for (int r = 0; r < 4; r++) {
                gs[r * 96 +  0 + lane] = fmaxf(g1[r], 0.f);
                gs[r * 96 + 32 + lane] = g2[r];
                gs[r * 96 + 64 + lane] = g3[r];
            }
            __syncwarp();
            if (lane == 0) {
                __threadfence_block();
                vprod[s * 2 + slot] = k;
            }
        }
    } else {
        // ===================== STREAMER warps =====================
        const int sw = w;
        const float b2v = sm[OFF_B2 + lane];
        const float b3v = sm[OFF_B3 + lane];

        for (int k = sw; ; k += NSTREAM) {
            const int gchunk = b + GRID * k;
            if (gchunk >= CHUNKS) break;
            const int row0 = gchunk * 4;
            const int slot = (k / NSTREAM) & 1;

            // ---- stream y FIRST (independent of producers) ----
            const float4* yb = (const float4*)(y + (size_t)row0 * ROW_F);
            float ys[4][NNv];
            #pragma unroll
            for (int rp = 0; rp < 2; rp++) {           // row pairs (2 rows each)
                float acc[2][NNv];
                #pragma unroll
                for (int r2 = 0; r2 < 2; r2++)
                    #pragma unroll
                    for (int n = 0; n < NNv; n++) acc[r2][n] = 0.f;
                // 80 independent loads, 10 accumulator chains
                #pragma unroll
                for (int i = 0; i < 8; i++)
                    #pragma unroll
                    for (int n = 0; n < NNv; n++)
                        #pragma unroll
                        for (int r2 = 0; r2 < 2; r2++) {
                            float4 v = __ldcs(yb + (size_t)(rp * 2 + r2) * 1280 + n * 256 + i * 32 + lane);
                            acc[r2][n] += (v.x + v.y) + (v.z + v.w);
                        }
                #pragma unroll
                for (int r2 = 0; r2 < 2; r2++)
                    #pragma unroll
                    for (int n = 0; n < NNv; n++)
                        ys[rp * 2 + r2][n] = warpsum(acc[r2][n]);
            }

            // ---- now get g's from producer ----
            while (vprod[sw * 2 + slot] != k) { }
            __threadfence_block();

            const float* gs = sm + OFF_GBUF + (sw * 2 + slot) * 384;
            float g1r[4], g2r[4], g3r[4];
            #pragma unroll
            for (int r = 0; r < 4; r++) {
                g1r[r] = gs[r * 96 +  0 + lane];
                g2r[r] = gs[r * 96 + 32 + lane];
                g3r[r] = gs[r * 96 + 64 + lane];
            }
            __syncwarp();
            if (lane == 0) {
                __threadfence_block();
                vcons[sw] = k;          // slot free
            }

            // ---- epilogue per row ----
            #pragma unroll
            for (int r = 0; r < 4; r++) {
                const int row = row0 + r;

                float sc[NNv];
                #pragma unroll
                for (int n = 0; n < NNv; n++)
                    sc[n] = warpsum(g1r[r] * fmaxf(fmaf(ys[r][n], g2r[r], b2v), 0.0f));

                float m = sc[0];
                #pragma unroll
                for (int n = 1; n < NNv; n++) m = fmaxf(m, sc[n]);
                float att[NNv], denom = 0.0f;
                #pragma unroll
                for (int n = 0; n < NNv; n++) { att[n] = __expf(sc[n] - m); denom += att[n]; }
                const float inv = 1.0f / denom;
                float sv = 0.0f;
                #pragma unroll
                for (int n = 0; n < NNv; n++) { att[n] *= inv; sv = fmaf(att[n], ys[r][n], sv); }

                const float ctxd = fmaf(sv, g3r[r], b3v);
                float la = 0.0f;
                #pragma unroll
                for (int a = 0; a < NACTv; a++) {
                    float p = warpsum(ctxd * sm[OFF_W4P + a * 32 + lane]);
                    if (lane == a) la = p;
                }
                if (lane < NACTv)
                    out[(size_t)row * NACTv + lane] = la + sm[OFF_B4P + lane];

                float av = 0.0f;
                #pragma unroll
                for (int n = 0; n < NNv; n++) if (lane == n) av = att[n];
                if (lane < NNv)
                    out[(size_t)ROWS * NACTv + (size_t)row * NNv + lane] = av;
            }
        }
    }
}

// ---------------------------------------------------------------------------
extern "C" void kernel_launch(void* const* d_in, const int* in_sizes, int n_in,
                              void* d_out, int out_size)
{
    const float* x   = (const float*)d_in[0];
    const float* y   = (const float*)d_in[1];
    const float* We0 = (const float*)d_in[2];
    const float* be0 = (const float*)d_in[3];
    const float* We1 = (const float*)d_in[4];
    const float* be1 = (const float*)d_in[5];
    const float* W1  = (const float*)d_in[6];
    const float* b1  = (const float*)d_in[7];
    const float* W2  = (const float*)d_in[8];
    const float* b2  = (const float*)d_in[9];
    const float* W3  = (const float*)d_in[10];
    const float* b3  = (const float*)d_in[11];
    const float* W4  = (const float*)d_in[12];
    const float* b4  = (const float*)d_in[13];
    const float* Wp  = (const float*)d_in[14];
    const float* bp  = (const float*)d_in[15];
    float* out = (float*)d_out;

    cudaFuncSetAttribute(fused_kernel, cudaFuncAttributeMaxDynamicSharedMemorySize, SMEM_BYTES);

    fused_kernel<<<GRID, NTHREADS, SMEM_BYTES>>>(
        x, y, We0, be0, We1, be1, W1, b1, W2, b2, W3, b3, W4, b4, Wp, bp, out);
}

// round 8
// speedup vs baseline: 1.2527x; 1.0500x over previous
#include <cuda_runtime.h>
#include <cstdint>

// Problem constants
#define NNv 5
#define NACTv 8
#define ROWS 32768
#define CHUNKS 8192               // chunks of 4 rows
#define ROW_F 5120                // floats per (b,j) row of y

#define NTHREADS 640              // 20 warps: 13 streamers + 7 MLP producers
#define NSTREAM 13
#define NMLP 7
#define GRID 152

// dynamic smem layout, offsets in floats
#define OFF_WE0  0          // 128*128 = 16384
#define OFF_WE1  16384      // 128*32  = 4096
#define OFF_W1   20480      // 32*32
#define OFF_W2   21504
#define OFF_W3   22528
#define OFF_W4P  23552      // [8][32] fused W4@Wp
#define OFF_W34  23808      // [32][8] (W3 @ W4p^T), e*8+a
#define OFF_BE0  24064      // 128
#define OFF_BE1  24192      // 32
#define OFF_B1   24224
#define OFF_B2   24256
#define OFF_B3   24288
#define OFF_B4P  24320      // 8 (b4@Wp+bp)
#define OFF_B34P 24352      // 8 (final fused bias)
#define OFF_GBUF 24384      // 13 streamers * 2 slots * 384 = 9984
#define OFF_XBUF 34368      // 7 mlp warps * 512 = 3584
#define OFF_PROD 37952      // 26 ints
#define OFF_CONS 37978      // 13 ints
#define SMEM_FLOATS 37992
#define SMEM_BYTES (SMEM_FLOATS * 4)   // ~148.4 KB

__device__ __forceinline__ float warpsum(float v) {
    v += __shfl_xor_sync(0xffffffffu, v, 16);
    v += __shfl_xor_sync(0xffffffffu, v, 8);
    v += __shfl_xor_sync(0xffffffffu, v, 4);
    v += __shfl_xor_sync(0xffffffffu, v, 2);
    v += __shfl_xor_sync(0xffffffffu, v, 1);
    return v;
}

__device__ __forceinline__ void fma4(float4& a, float s, const float4& w) {
    a.x = fmaf(s, w.x, a.x);
    a.y = fmaf(s, w.y, a.y);
    a.z = fmaf(s, w.z, a.z);
    a.w = fmaf(s, w.w, a.w);
}

__global__ __launch_bounds__(NTHREADS, 1) void fused_kernel(
    const float* __restrict__ x,
    const float* __restrict__ y,
    const float* __restrict__ We0, const float* __restrict__ be0,
    const float* __restrict__ We1, const float* __restrict__ be1,
    const float* __restrict__ W1, const float* __restrict__ b1,
    const float* __restrict__ W2, const float* __restrict__ b2,
    const float* __restrict__ W3, const float* __restrict__ b3,
    const float* __restrict__ W4, const float* __restrict__ b4,
    const float* __restrict__ Wp, const float* __restrict__ bp,
    float* __restrict__ out)
{
    extern __shared__ float sm[];
    const int tid  = threadIdx.x;
    const int lane = tid & 31;
    const int w    = tid >> 5;
    const int b    = blockIdx.x;

    // ---- stage A: weights into smem + first-level fusions ----
    for (int i = tid; i < 16384; i += NTHREADS) sm[OFF_WE0 + i] = We0[i];
    for (int i = tid; i < 4096;  i += NTHREADS) sm[OFF_WE1 + i] = We1[i];
    for (int i = tid; i < 1024;  i += NTHREADS) {
        sm[OFF_W1 + i] = W1[i];
        sm[OFF_W2 + i] = W2[i];
        sm[OFF_W3 + i] = W3[i];
    }
    // W4p[a][e] = sum_k W4[e][k]*Wp[k][a]
    if (tid < 256) {
        const int a = tid >> 5, e = tid & 31;
        float acc = 0.f;
        #pragma unroll 8
        for (int k = 0; k < 32; k++)
            acc = fmaf(W4[e * 32 + k], Wp[k * NACTv + a], acc);
        sm[OFF_W4P + a * 32 + e] = acc;
    }
    if (tid < 128) sm[OFF_BE0 + tid] = be0[tid];
    if (tid < 32) {
        sm[OFF_BE1 + tid] = be1[tid];
        sm[OFF_B1 + tid] = b1[tid];
        sm[OFF_B2 + tid] = b2[tid];
        sm[OFF_B3 + tid] = b3[tid];
        if (tid < 8) {
            float acc = bp[tid];
            #pragma unroll 8
            for (int k = 0; k < 32; k++)
                acc = fmaf(b4[k], Wp[k * NACTv + tid], acc);
            sm[OFF_B4P + tid] = acc;
        }
    }
    // flags
    int* prod = (int*)(sm + OFF_PROD);
    int* cons = (int*)(sm + OFF_CONS);
    if (tid < 26) prod[tid] = -1;
    if (tid < 13) cons[tid] = -1;
    __syncthreads();

    // ---- stage B: second-level fusions (need W4p, W3, b3 in smem) ----
    // W34t[e][a] = sum_d W3[e][d] * W4p[a][d]
    if (tid < 256) {
        const int e = tid >> 3, a = tid & 7;
        float acc = 0.f;
        #pragma unroll 8
        for (int d = 0; d < 32; d++)
            acc = fmaf(sm[OFF_W3 + e * 32 + d], sm[OFF_W4P + a * 32 + d], acc);
        sm[OFF_W34 + e * 8 + a] = acc;
    }
    if (tid < 8) {
        float acc = sm[OFF_B4P + tid];
        #pragma unroll 8
        for (int d = 0; d < 32; d++)
            acc = fmaf(sm[OFF_B3 + d], sm[OFF_W4P + tid * 32 + d], acc);
        sm[OFF_B34P + tid] = acc;
    }
    __syncthreads();

    volatile int* vprod = (volatile int*)prod;
    volatile int* vcons = (volatile int*)cons;

    if (w >= NSTREAM) {
        // ===================== PRODUCER (MLP) warps =====================
        const int mw = w - NSTREAM;
        const float4* We0s4 = (const float4*)(sm + OFF_WE0);
        const float4* be0s4 = (const float4*)(sm + OFF_BE0);
        float4* xb4 = (float4*)(sm + OFF_XBUF) + mw * 128;
        const float b1v  = sm[OFF_B1 + lane];
        const float be1v = sm[OFF_BE1 + lane];
        const int la8 = lane & 7;

        for (int k = mw; ; k += NMLP) {
            const int gchunk = b + GRID * k;
            if (gchunk >= CHUNKS) break;
            const int row0 = gchunk * 4;
            const int s = k % NSTREAM;
            const int slot = (k / NSTREAM) & 1;

            // wait for slot free
            while (vcons[s] < k - 2 * NSTREAM) { __nanosleep(100); }

            // stage x
            #pragma unroll
            for (int r = 0; r < 4; r++)
                xb4[r * 32 + lane] = __ldcs(((const float4*)(x)) + (size_t)(row0 + r) * 32 + lane);
            __syncwarp();

            // layer 0
            float4 acc0 = be0s4[lane], acc1 = acc0, acc2 = acc0, acc3 = acc0;
            #pragma unroll 8
            for (int k4 = 0; k4 < 32; k4++) {
                float4 w0 = We0s4[(k4 * 4 + 0) * 32 + lane];
                float4 w1 = We0s4[(k4 * 4 + 1) * 32 + lane];
                float4 w2 = We0s4[(k4 * 4 + 2) * 32 + lane];
                float4 w3 = We0s4[(k4 * 4 + 3) * 32 + lane];
                float4 xk;
                xk = xb4[0 * 32 + k4];
                fma4(acc0, xk.x, w0); fma4(acc0, xk.y, w1); fma4(acc0, xk.z, w2); fma4(acc0, xk.w, w3);
                xk = xb4[1 * 32 + k4];
                fma4(acc1, xk.x, w0); fma4(acc1, xk.y, w1); fma4(acc1, xk.z, w2); fma4(acc1, xk.w, w3);
                xk = xb4[2 * 32 + k4];
                fma4(acc2, xk.x, w0); fma4(acc2, xk.y, w1); fma4(acc2, xk.z, w2); fma4(acc2, xk.w, w3);
                xk = xb4[3 * 32 + k4];
                fma4(acc3, xk.x, w0); fma4(acc3, xk.y, w1); fma4(acc3, xk.z, w2); fma4(acc3, xk.w, w3);
            }
            __syncwarp();
            acc0.x = fmaxf(acc0.x, 0.f); acc0.y = fmaxf(acc0.y, 0.f); acc0.z = fmaxf(acc0.z, 0.f); acc0.w = fmaxf(acc0.w, 0.f);
            acc1.x = fmaxf(acc1.x, 0.f); acc1.y = fmaxf(acc1.y, 0.f); acc1.z = fmaxf(acc1.z, 0.f); acc1.w = fmaxf(acc1.w, 0.f);
            acc2.x = fmaxf(acc2.x, 0.f); acc2.y = fmaxf(acc2.y, 0.f); acc2.z = fmaxf(acc2.z, 0.f); acc2.w = fmaxf(acc2.w, 0.f);
            acc3.x = fmaxf(acc3.x, 0.f); acc3.y = fmaxf(acc3.y, 0.f); acc3.z = fmaxf(acc3.z, 0.f); acc3.w = fmaxf(acc3.w, 0.f);
            xb4[0 * 32 + lane] = acc0;
            xb4[1 * 32 + lane] = acc1;
            xb4[2 * 32 + lane] = acc2;
            xb4[3 * 32 + lane] = acc3;
            __syncwarp();

            // layer 1
            float a1_0 = be1v, a1_1 = be1v, a1_2 = be1v, a1_3 = be1v;
            #pragma unroll 8
            for (int k4 = 0; k4 < 32; k4++) {
                float w0 = sm[OFF_WE1 + (k4 * 4 + 0) * 32 + lane];
                float w1 = sm[OFF_WE1 + (k4 * 4 + 1) * 32 + lane];
                float w2 = sm[OFF_WE1 + (k4 * 4 + 2) * 32 + lane];
                float w3 = sm[OFF_WE1 + (k4 * 4 + 3) * 32 + lane];
                float4 hk;
                hk = xb4[0 * 32 + k4];
                a1_0 = fmaf(hk.x, w0, a1_0); a1_0 = fmaf(hk.y, w1, a1_0); a1_0 = fmaf(hk.z, w2, a1_0); a1_0 = fmaf(hk.w, w3, a1_0);
                hk = xb4[1 * 32 + k4];
                a1_1 = fmaf(hk.x, w0, a1_1); a1_1 = fmaf(hk.y, w1, a1_1); a1_1 = fmaf(hk.z, w2, a1_1); a1_1 = fmaf(hk.w, w3, a1_1);
                hk = xb4[2 * 32 + k4];
                a1_2 = fmaf(hk.x, w0, a1_2); a1_2 = fmaf(hk.y, w1, a1_2); a1_2 = fmaf(hk.z, w2, a1_2); a1_2 = fmaf(hk.w, w3, a1_2);
                hk = xb4[3 * 32 + k4];
                a1_3 = fmaf(hk.x, w0, a1_3); a1_3 = fmaf(hk.y, w1, a1_3); a1_3 = fmaf(hk.z, w2, a1_3); a1_3 = fmaf(hk.w, w3, a1_3);
            }
            float h[4];
            h[0] = fmaxf(a1_0, 0.f); h[1] = fmaxf(a1_1, 0.f);
            h[2] = fmaxf(a1_2, 0.f); h[3] = fmaxf(a1_3, 0.f);

            // g1/g2 across lanes; q on lanes 0..7 (head fully folded)
            float g1[4], g2[4], q[4];
            #pragma unroll
            for (int r = 0; r < 4; r++) { g1[r] = b1v; g2[r] = 0.f; q[r] = 0.f; }
            #pragma unroll 8
            for (int e = 0; e < 32; e++) {
                const float w1e  = sm[OFF_W1 + e * 32 + lane];
                const float w2e  = sm[OFF_W2 + e * 32 + lane];
                const float w34e = sm[OFF_W34 + e * 8 + la8];
                #pragma unroll
                for (int r = 0; r < 4; r++) {
                    const float he = __shfl_sync(0xffffffffu, h[r], e);
                    g1[r] = fmaf(he, w1e, g1[r]);
                    g2[r] = fmaf(he, w2e, g2[r]);
                    q[r]  = fmaf(he, w34e, q[r]);
                }
            }

            // publish to slot: per row g1(32) g2(32) q(8)
            float* gs = sm + OFF_GBUF + (s * 2 + slot) * 384;
            #pragma unroll
            for (int r = 0; r < 4; r++) {
                gs[r * 96 +  0 + lane] = fmaxf(g1[r], 0.f);
                gs[r * 96 + 32 + lane] = g2[r];
                if (lane < 8) gs[r * 96 + 64 + lane] = q[r];
            }
            __syncwarp();
            if (lane == 0) {
                __threadfence_block();
                vprod[s * 2 + slot] = k;
            }
        }
    } else {
        // ===================== STREAMER warps =====================
        const int sw = w;
        const float b2v = sm[OFF_B2 + lane];
        const float b34pv = sm[OFF_B34P + (lane & 7)];

        for (int k = sw; ; k += NSTREAM) {
            const int gchunk = b + GRID * k;
            if (gchunk >= CHUNKS) break;
            const int row0 = gchunk * 4;
            const int slot = (k / NSTREAM) & 1;

            // ---- stream y FIRST (independent of producers) ----
            const float4* yb = (const float4*)(y + (size_t)row0 * ROW_F);
            float ys[4][NNv];
            #pragma unroll
            for (int rp = 0; rp < 2; rp++) {
                float acc[2][NNv];
                #pragma unroll
                for (int r2 = 0; r2 < 2; r2++)
                    #pragma unroll
                    for (int n = 0; n < NNv; n++) acc[r2][n] = 0.f;
                #pragma unroll
                for (int i = 0; i < 8; i++)
                    #pragma unroll
                    for (int n = 0; n < NNv; n++)
                        #pragma unroll
                        for (int r2 = 0; r2 < 2; r2++) {
                            float4 v = __ldcs(yb + (size_t)(rp * 2 + r2) * 1280 + n * 256 + i * 32 + lane);
                            acc[r2][n] += (v.x + v.y) + (v.z + v.w);
                        }
                #pragma unroll
                for (int r2 = 0; r2 < 2; r2++)
                    #pragma unroll
                    for (int n = 0; n < NNv; n++)
                        ys[rp * 2 + r2][n] = warpsum(acc[r2][n]);
            }

            // ---- get g's from producer ----
            while (vprod[sw * 2 + slot] != k) { __nanosleep(60); }
            __threadfence_block();

            const float* gs = sm + OFF_GBUF + (sw * 2 + slot) * 384;
            float g1r[4], g2r[4], qr[4];
            #pragma unroll
            for (int r = 0; r < 4; r++) {
                g1r[r] = gs[r * 96 +  0 + lane];
                g2r[r] = gs[r * 96 + 32 + lane];
                qr[r]  = gs[r * 96 + 64 + (lane & 7)];
            }
            __syncwarp();
            if (lane == 0) {
                __threadfence_block();
                vcons[sw] = k;          // slot free
            }

            // ---- epilogue per row (no head warpsums) ----
            #pragma unroll
            for (int r = 0; r < 4; r++) {
                const int row = row0 + r;

                float sc[NNv];
                #pragma unroll
                for (int n = 0; n < NNv; n++)
                    sc[n] = warpsum(g1r[r] * fmaxf(fmaf(ys[r][n], g2r[r], b2v), 0.0f));

                float m = sc[0];
                #pragma unroll
                for (int n = 1; n < NNv; n++) m = fmaxf(m, sc[n]);
                float att[NNv], denom = 0.0f;
                #pragma unroll
                for (int n = 0; n < NNv; n++) { att[n] = __expf(sc[n] - m); denom += att[n]; }
                const float inv = 1.0f / denom;
                float sv = 0.0f;
                #pragma unroll
                for (int n = 0; n < NNv; n++) { att[n] *= inv; sv = fmaf(att[n], ys[r][n], sv); }

                if (lane < NACTv)
                    out[(size_t)row * NACTv + lane] = fmaf(sv, qr[r], b34pv);

                float av = 0.0f;
                #pragma unroll
                for (int n = 0; n < NNv; n++) if (lane == n) av = att[n];
                if (lane < NNv)
                    out[(size_t)ROWS * NACTv + (size_t)row * NNv + lane] = av;
            }
        }
    }
}

// ---------------------------------------------------------------------------
extern "C" void kernel_launch(void* const* d_in, const int* in_sizes, int n_in,
                              void* d_out, int out_size)
{
    const float* x   = (const float*)d_in[0];
    const float* y   = (const float*)d_in[1];
    const float* We0 = (const float*)d_in[2];
    const float* be0 = (const float*)d_in[3];
    const float* We1 = (const float*)d_in[4];
    const float* be1 = (const float*)d_in[5];
    const float* W1  = (const float*)d_in[6];
    const float* b1  = (const float*)d_in[7];
    const float* W2  = (const float*)d_in[8];
    const float* b2  = (const float*)d_in[9];
    const float* W3  = (const float*)d_in[10];
    const float* b3  = (const float*)d_in[11];
    const float* W4  = (const float*)d_in[12];
    const float* b4  = (const float*)d_in[13];
    const float* Wp  = (const float*)d_in[14];
    const float* bp  = (const float*)d_in[15];
    float* out = (float*)d_out;

    cudaFuncSetAttribute(fused_kernel, cudaFuncAttributeMaxDynamicSharedMemorySize, SMEM_BYTES);

    fused_kernel<<<GRID, NTHREADS, SMEM_BYTES>>>(
        x, y, We0, be0, We1, be1, W1, b1, W2, b2, W3, b3, W4, b4, Wp, bp, out);
}